// round 1
// baseline (speedup 1.0000x reference)
#include <cuda_runtime.h>
#include <math.h>

#define TT 4096
#define KDIM (64*4096)   /* 262144 */
#define MROWS 320
#define FD 512

// ---------------- scratch (static device globals; no allocation) ----------------
__device__ float g_A[(size_t)MROWS * KDIM];   // 5 views stacked: row r = v*64+b, col c*4096+t
__device__ float g_feats[MROWS * FD];
__device__ float g_norms[MROWS];
__device__ float g_cons;
__device__ float g_contr;

// ---------------- helpers ----------------
__device__ __forceinline__ float2 cmul(float2 a, float2 b) {
    return make_float2(a.x*b.x - a.y*b.y, a.x*b.y + a.y*b.x);
}

__device__ __forceinline__ float blockReduceSum(float v, float* red) {
    int lane = threadIdx.x & 31, w = threadIdx.x >> 5;
    int nw = blockDim.x >> 5;
    #pragma unroll
    for (int o = 16; o; o >>= 1) v += __shfl_down_sync(0xffffffffu, v, o);
    if (lane == 0) red[w] = v;
    __syncthreads();
    if (w == 0) {
        float r = (lane < nw) ? red[lane] : 0.0f;
        #pragma unroll
        for (int o = 8; o; o >>= 1) r += __shfl_down_sync(0xffffffffu, r, o);
        if (lane == 0) red[0] = r;
    }
    __syncthreads();
    float out = red[0];
    __syncthreads();
    return out;
}

__device__ __forceinline__ float blockReduceMax(float v, float* red) {
    int lane = threadIdx.x & 31, w = threadIdx.x >> 5;
    int nw = blockDim.x >> 5;
    #pragma unroll
    for (int o = 16; o; o >>= 1) v = fmaxf(v, __shfl_down_sync(0xffffffffu, v, o));
    if (lane == 0) red[w] = v;
    __syncthreads();
    if (w == 0) {
        float r = (lane < nw) ? red[lane] : -3.4e38f;
        #pragma unroll
        for (int o = 8; o; o >>= 1) r = fmaxf(r, __shfl_down_sync(0xffffffffu, r, o));
        if (lane == 0) red[0] = r;
    }
    __syncthreads();
    float out = red[0];
    __syncthreads();
    return out;
}

// spectrum masks. mid=0: compress(level 0.5); mid=1: fmask; mid=2: g(level 0.25 real-part-fold)*fmask
template<int MID>
__device__ __forceinline__ float maskval(int k, int fs) {
    float fm = (k >= fs && k < fs + 409) ? 0.1f : 1.0f;  // fw = int(0.1*4096) = 409
    if (MID == 0) return (k < 2048) ? 1.0f : 0.0f;
    if (MID == 1) return fm;
    float g = (k == 0) ? 1.0f : ((k <= 1024) ? 0.5f : ((k < 3072) ? 1.0f : 0.5f));
    return g * fm;
}

// radix-2 Stockham, N=4096, 12 stages, ping-pong b0/b1, result ends in b0.
__device__ float2* fft_fwd(const float2* __restrict__ tw, float2* b0, float2* b1) {
    float2* src = b0; float2* dst = b1;
    #pragma unroll 1
    for (int s = 0; s < 12; s++) {
        int m = 1 << s;
        __syncthreads();
        #pragma unroll
        for (int i = threadIdx.x; i < 2048; i += 512) {
            int jm = i & ~(m - 1);               // j << s
            float2 a = src[i];
            float2 b = src[i + 2048];
            float2 w = tw[jm];
            int d0 = i + jm;
            dst[d0] = make_float2(a.x + b.x, a.y + b.y);
            float2 d = make_float2(a.x - b.x, a.y - b.y);
            dst[d0 + m] = cmul(d, w);
        }
        float2* t = src; src = dst; dst = t;
    }
    __syncthreads();
    return src;  // = b0 (12 swaps)
}

// masked inverse FFT: stage0 reads X (preserved) with mask applied, then 11 stages b1<->b2.
// Returns pointer to result (== b2). Unnormalized (caller multiplies by 1/4096).
template<int MID>
__device__ float2* ifft_masked(const float2* __restrict__ tw, const float2* __restrict__ X,
                               float2* b1, float2* b2, int fs) {
    __syncthreads();
    #pragma unroll
    for (int i = threadIdx.x; i < 2048; i += 512) {
        float m0 = maskval<MID>(i, fs);
        float m1 = maskval<MID>(i + 2048, fs);
        float2 a = X[i];        a.x *= m0; a.y *= m0;
        float2 b = X[i + 2048]; b.x *= m1; b.y *= m1;
        float2 w = tw[i]; w.y = -w.y;    // conj for inverse
        b1[2*i]   = make_float2(a.x + b.x, a.y + b.y);
        float2 d = make_float2(a.x - b.x, a.y - b.y);
        b1[2*i+1] = cmul(d, w);
    }
    float2* src = b1; float2* dst = b2;
    #pragma unroll 1
    for (int s = 1; s < 12; s++) {
        int m = 1 << s;
        __syncthreads();
        #pragma unroll
        for (int i = threadIdx.x; i < 2048; i += 512) {
            int jm = i & ~(m - 1);
            float2 a = src[i];
            float2 b = src[i + 2048];
            float2 w = tw[jm]; w.y = -w.y;
            int d0 = i + jm;
            dst[d0] = make_float2(a.x + b.x, a.y + b.y);
            float2 d = make_float2(a.x - b.x, a.y - b.y);
            dst[d0 + m] = cmul(d, w);
        }
        float2* t = src; src = dst; dst = t;
    }
    __syncthreads();
    return src;  // = b2 (11 swaps from b1)
}

// ---------------- kernel 0: init feats=b, accumulators=0 ----------------
__global__ void init_kernel(const float* __restrict__ b) {
    int i = blockIdx.x * blockDim.x + threadIdx.x;
    if (i < MROWS * FD) g_feats[i] = b[i & 511];
    if (i == 0) { g_cons = 0.0f; g_contr = 0.0f; }
}

// ---------------- kernel 1: build all 5 views (one block per (b,c) row) ----------------
__global__ void __launch_bounds__(512, 1)
views_kernel(const float* __restrict__ x, const float* __restrict__ nz1,
             const float* __restrict__ nz2,
             const int* __restrict__ pfs, const int* __restrict__ pts) {
    extern __shared__ float2 smx[];
    float2* tw = smx;            // 2048
    float2* bA = smx + 2048;     // 4096 (holds X)
    float2* bB = bA + 4096;      // 4096
    float2* bC = bB + 4096;      // 4096
    __shared__ float red[32];

    const int row = blockIdx.x;          // b*64 + c
    const int bi = row >> 6, ci = row & 63;
    const int tid = threadIdx.x;
    const int fs = *pfs, ts = *pts;
    const size_t xbase = (size_t)row * TT;

    float* A0 = g_A + (size_t)(0*64 + bi) * KDIM + (size_t)ci * TT;  // original
    float* A1 = g_A + (size_t)(1*64 + bi) * KDIM + (size_t)ci * TT;  // compressed
    float* A2 = g_A + (size_t)(2*64 + bi) * KDIM + (size_t)ci * TT;  // distorted
    float* A3 = g_A + (size_t)(3*64 + bi) * KDIM + (size_t)ci * TT;  // noisy
    float* A4 = g_A + (size_t)(4*64 + bi) * KDIM + (size_t)ci * TT;  // combined

    // twiddles: tw[k] = exp(-i*pi*k/2048)
    for (int k = tid; k < 2048; k += 512) {
        float s, c;
        sincospif(-(float)k * (1.0f / 2048.0f), &s, &c);
        tw[k] = make_float2(c, s);
    }

    // load x row, write view0, accumulate std stats
    float ls = 0.0f, lq = 0.0f;
    for (int t = tid; t < TT; t += 512) {
        float v = x[xbase + t];
        bA[t] = make_float2(v, 0.0f);
        A0[t] = v;
        ls += v; lq += v * v;
    }
    float s1 = blockReduceSum(ls, red);
    float q1 = blockReduceSum(lq, red);
    float std1 = sqrtf(fmaxf(0.0f, (q1 - s1 * s1 * (1.0f / 4096.0f)) * (1.0f / 4095.0f)));

    // noisy view (view3)
    for (int t = tid; t < TT; t += 512)
        A3[t] = x[xbase + t] + nz1[xbase + t] * (0.02f * std1);

    // forward FFT of x row -> X stays in bA
    fft_fwd(tw, bA, bB);

    // view1: compressed (level 0.5)
    float2* r = ifft_masked<0>(tw, bA, bB, bC, fs);
    for (int t = tid; t < TT; t += 512)
        A1[t] = r[t].x * (1.0f / 4096.0f);

    // view2: distorted
    r = ifft_masked<1>(tw, bA, bB, bC, fs);
    for (int t = tid; t < TT; t += 512) {
        float tm = (t >= ts && t < ts + 204) ? 0.1f : 1.0f;  // tw = int(0.05*4096) = 204
        A2[t] = tm * r[t].x * (1.0f / 4096.0f);
    }

    // view4: combined = add_noise(distort(compress(x,0.25)))
    r = ifft_masked<2>(tw, bA, bB, bC, fs);
    ls = 0.0f; lq = 0.0f;
    for (int t = tid; t < TT; t += 512) {
        float tm = (t >= ts && t < ts + 204) ? 0.1f : 1.0f;
        float v = tm * r[t].x * (1.0f / 4096.0f);
        ls += v; lq += v * v;
    }
    float s2 = blockReduceSum(ls, red);
    float q2 = blockReduceSum(lq, red);
    float std2 = sqrtf(fmaxf(0.0f, (q2 - s2 * s2 * (1.0f / 4096.0f)) * (1.0f / 4095.0f)));
    for (int t = tid; t < TT; t += 512) {
        float tm = (t >= ts && t < ts + 204) ? 0.1f : 1.0f;
        float v = tm * r[t].x * (1.0f / 4096.0f);
        A4[t] = v + nz2[xbase + t] * (0.02f * std2);
    }
}

// ---------------- kernel 2: split-K fp32 GEMM  feats += A[320,K] * W[K,512] ----------------
#define SPLITK 16
#define KCHUNK (KDIM / SPLITK)   /* 16384 */

__global__ void __launch_bounds__(256, 4)
gemm_kernel(const float* __restrict__ Wm) {
    __shared__ float As[32][64];   // [k][m]
    __shared__ float Bs[32][64];   // [k][n]

    const int tid = threadIdx.x;
    const int m0 = blockIdx.y << 6;
    const int n0 = blockIdx.x << 6;
    const size_t k0 = (size_t)blockIdx.z * KCHUNK;

    const int ar  = tid >> 3;            // 0..31
    const int ac  = (tid & 7) << 2;      // 0..28
    const int bcr = tid >> 4;            // 0..15
    const int bn  = (tid & 15) << 2;     // 0..60

    const int tm = (tid >> 4) << 2;      // 0..60
    const int tn = (tid & 15) << 2;      // 0..60

    float acc[4][4] = {};

    const float* Ab0 = g_A + (size_t)(m0 + ar) * KDIM;
    const float* Ab1 = g_A + (size_t)(m0 + ar + 32) * KDIM;

    for (size_t kk = k0; kk < k0 + KCHUNK; kk += 32) {
        float4 a0 = *(const float4*)(Ab0 + kk + ac);
        float4 a1 = *(const float4*)(Ab1 + kk + ac);
        float4 w0 = *(const float4*)(Wm + (kk + bcr) * 512 + n0 + bn);
        float4 w1 = *(const float4*)(Wm + (kk + bcr + 16) * 512 + n0 + bn);
        __syncthreads();
        As[ac + 0][ar] = a0.x; As[ac + 1][ar] = a0.y; As[ac + 2][ar] = a0.z; As[ac + 3][ar] = a0.w;
        As[ac + 0][ar + 32] = a1.x; As[ac + 1][ar + 32] = a1.y; As[ac + 2][ar + 32] = a1.z; As[ac + 3][ar + 32] = a1.w;
        *(float4*)&Bs[bcr][bn] = w0;
        *(float4*)&Bs[bcr + 16][bn] = w1;
        __syncthreads();
        #pragma unroll
        for (int c = 0; c < 32; c++) {
            float4 av = *(const float4*)&As[c][tm];
            float4 bv = *(const float4*)&Bs[c][tn];
            acc[0][0] += av.x * bv.x; acc[0][1] += av.x * bv.y; acc[0][2] += av.x * bv.z; acc[0][3] += av.x * bv.w;
            acc[1][0] += av.y * bv.x; acc[1][1] += av.y * bv.y; acc[1][2] += av.y * bv.z; acc[1][3] += av.y * bv.w;
            acc[2][0] += av.z * bv.x; acc[2][1] += av.z * bv.y; acc[2][2] += av.z * bv.z; acc[2][3] += av.z * bv.w;
            acc[3][0] += av.w * bv.x; acc[3][1] += av.w * bv.y; acc[3][2] += av.w * bv.z; acc[3][3] += av.w * bv.w;
        }
    }

    #pragma unroll
    for (int i = 0; i < 4; i++)
        #pragma unroll
        for (int j = 0; j < 4; j++)
            atomicAdd(&g_feats[(m0 + tm + i) * 512 + n0 + tn + j], acc[i][j]);
}

// ---------------- kernel 3: row norms + consistency accumulation ----------------
__global__ void post_kernel() {
    __shared__ float red[32];
    const int i = blockIdx.x;            // 0..319
    const int tid = threadIdx.x;         // 256
    const int base = i * 512;
    const int b0 = (i & 63) * 512;       // matching row of view 0
    float sq = 0.0f, dsq = 0.0f;
    for (int f = tid; f < 512; f += 256) {
        float v = g_feats[base + f];
        sq += v * v;
        if (i >= 64) {
            float d = v - g_feats[b0 + f];
            dsq += d * d;
        }
    }
    float tsq = blockReduceSum(sq, red);
    float tdq = blockReduceSum(dsq, red);
    if (tid == 0) {
        g_norms[i] = sqrtf(tsq);
        if (i >= 64) atomicAdd(&g_cons, tdq);
    }
}

// ---------------- kernel 4: contrastive (one block per row of sim) ----------------
__global__ void contr_kernel() {
    __shared__ float fi[512];
    __shared__ float simb[320];
    __shared__ float red[32];
    const int i = blockIdx.x;            // 0..319
    const int tid = threadIdx.x;         // 256
    for (int f = tid; f < 512; f += 256) fi[f] = g_feats[i * 512 + f];
    __syncthreads();
    const float inv_i = 1.0f / g_norms[i];
    const int w = tid >> 5, lane = tid & 31;
    for (int j = w; j < 320; j += 8) {
        float s = 0.0f;
        const float* fj = g_feats + j * 512;
        #pragma unroll 4
        for (int e = lane; e < 512; e += 32) s += fi[e] * fj[e];
        #pragma unroll
        for (int o = 16; o; o >>= 1) s += __shfl_down_sync(0xffffffffu, s, o);
        if (lane == 0) simb[j] = s * inv_i / g_norms[j] * 10.0f;  // /TEMPERATURE
    }
    __syncthreads();
    float mx = -3.4e38f;
    for (int j = tid; j < 320; j += 256) mx = fmaxf(mx, simb[j]);
    mx = blockReduceMax(mx, red);
    float se = 0.0f;
    for (int j = tid; j < 320; j += 256) se += expf(simb[j] - mx);
    se = blockReduceSum(se, red);
    if (tid == 0) {
        float lse = mx + logf(se);
        float c = 0.0f;
        if (i > 0)   c += lse - simb[i - 1];
        if (i < 319) c += lse - simb[i + 1];
        atomicAdd(&g_contr, c);
    }
}

// ---------------- kernel 5: finalize scalar ----------------
__global__ void fin_kernel(float* __restrict__ out) {
    out[0] = g_cons * (1.0f / 131072.0f) + 0.5f * (g_contr * (1.0f / 638.0f));
}

// ---------------- launch ----------------
extern "C" void kernel_launch(void* const* d_in, const int* in_sizes, int n_in,
                              void* d_out, int out_size) {
    const float* x  = (const float*)d_in[0];
    const float* W  = (const float*)d_in[1];
    const float* b  = (const float*)d_in[2];
    const float* n1 = (const float*)d_in[3];
    const float* n2 = (const float*)d_in[4];
    const int* fs   = (const int*)d_in[5];
    const int* ts   = (const int*)d_in[6];
    (void)in_sizes; (void)n_in; (void)out_size;

    cudaFuncSetAttribute(views_kernel, cudaFuncAttributeMaxDynamicSharedMemorySize, 114688);

    init_kernel<<<640, 256>>>(b);
    views_kernel<<<4096, 512, 114688>>>(x, n1, n2, fs, ts);
    gemm_kernel<<<dim3(8, 5, SPLITK), 256>>>(W);
    post_kernel<<<320, 256>>>();
    contr_kernel<<<320, 256>>>();
    fin_kernel<<<1, 1>>>((float*)d_out);
}

// round 3
// speedup vs baseline: 2.8264x; 2.8264x over previous
#include <cuda_runtime.h>
#include <cuda_bf16.h>
#include <math.h>
#include <stdint.h>

#define TT 4096
#define KTOT (64*4096)   /* 262144 */
#define FD 512

// ---------------- scratch (static device globals) ----------------
__device__ float g_A[(size_t)320 * KTOT];   // 5 views stacked: row r = v*64+b
__device__ float g_feats[320 * FD];
__device__ float g_norms[320];
__device__ float g_cons;
__device__ float g_contr;

// ---------------- small PTX helpers (baseline ISA only) ----------------
__device__ __forceinline__ uint32_t smem_to_u32(const void* p) {
    uint32_t a;
    asm("{ .reg .u64 t; cvta.to.shared.u64 t, %1; cvt.u32.u64 %0, t; }" : "=r"(a) : "l"(p));
    return a;
}
__device__ __forceinline__ void ldsm_x4(uint32_t* r, uint32_t addr) {
    asm volatile("ldmatrix.sync.aligned.m8n8.x4.shared.b16 {%0,%1,%2,%3}, [%4];"
        : "=r"(r[0]), "=r"(r[1]), "=r"(r[2]), "=r"(r[3]) : "r"(addr));
}
__device__ __forceinline__ void ldsm_x2_trans(uint32_t* r, uint32_t addr) {
    asm volatile("ldmatrix.sync.aligned.m8n8.x2.trans.shared.b16 {%0,%1}, [%2];"
        : "=r"(r[0]), "=r"(r[1]) : "r"(addr));
}
__device__ __forceinline__ void mma_bf16(float* c, const uint32_t* a, const uint32_t* b) {
    asm volatile("mma.sync.aligned.m16n8k16.row.col.f32.bf16.bf16.f32 "
        "{%0,%1,%2,%3}, {%4,%5,%6,%7}, {%8,%9}, {%0,%1,%2,%3};"
        : "+f"(c[0]), "+f"(c[1]), "+f"(c[2]), "+f"(c[3])
        : "r"(a[0]), "r"(a[1]), "r"(a[2]), "r"(a[3]), "r"(b[0]), "r"(b[1]));
}
__device__ __forceinline__ void split2(float x, float y, uint32_t& hi, uint32_t& lo) {
    __nv_bfloat16 hx = __float2bfloat16_rn(x);
    __nv_bfloat16 hy = __float2bfloat16_rn(y);
    __nv_bfloat162 h; h.x = hx; h.y = hy;
    hi = *reinterpret_cast<const uint32_t*>(&h);
    __nv_bfloat162 l;
    l.x = __float2bfloat16_rn(x - __bfloat162float(hx));
    l.y = __float2bfloat16_rn(y - __bfloat162float(hy));
    lo = *reinterpret_cast<const uint32_t*>(&l);
}

// ---------------- block reductions ----------------
__device__ __forceinline__ float blockReduceSum(float v, float* red) {
    int lane = threadIdx.x & 31, w = threadIdx.x >> 5;
    int nw = blockDim.x >> 5;
    #pragma unroll
    for (int o = 16; o; o >>= 1) v += __shfl_down_sync(0xffffffffu, v, o);
    if (lane == 0) red[w] = v;
    __syncthreads();
    if (w == 0) {
        float r = (lane < nw) ? red[lane] : 0.0f;
        #pragma unroll
        for (int o = 8; o; o >>= 1) r += __shfl_down_sync(0xffffffffu, r, o);
        if (lane == 0) red[0] = r;
    }
    __syncthreads();
    float out = red[0];
    __syncthreads();
    return out;
}
__device__ __forceinline__ float blockReduceMax(float v, float* red) {
    int lane = threadIdx.x & 31, w = threadIdx.x >> 5;
    int nw = blockDim.x >> 5;
    #pragma unroll
    for (int o = 16; o; o >>= 1) v = fmaxf(v, __shfl_down_sync(0xffffffffu, v, o));
    if (lane == 0) red[w] = v;
    __syncthreads();
    if (w == 0) {
        float r = (lane < nw) ? red[lane] : -3.4e38f;
        #pragma unroll
        for (int o = 8; o; o >>= 1) r = fmaxf(r, __shfl_down_sync(0xffffffffu, r, o));
        if (lane == 0) red[0] = r;
    }
    __syncthreads();
    float out = red[0];
    __syncthreads();
    return out;
}

// ---------------- FFT pieces (proven in R1) ----------------
__device__ __forceinline__ float2 cmul(float2 a, float2 b) {
    return make_float2(a.x*b.x - a.y*b.y, a.x*b.y + a.y*b.x);
}
template<int MID>
__device__ __forceinline__ float maskval(int k, int fs) {
    float fm = (k >= fs && k < fs + 409) ? 0.1f : 1.0f;
    if (MID == 0) return (k < 2048) ? 1.0f : 0.0f;
    if (MID == 1) return fm;
    float g = (k == 0) ? 1.0f : ((k <= 1024) ? 0.5f : ((k < 3072) ? 1.0f : 0.5f));
    return g * fm;
}
__device__ float2* fft_fwd(const float2* __restrict__ tw, float2* b0, float2* b1) {
    float2* src = b0; float2* dst = b1;
    #pragma unroll 1
    for (int s = 0; s < 12; s++) {
        int m = 1 << s;
        __syncthreads();
        #pragma unroll
        for (int i = threadIdx.x; i < 2048; i += 512) {
            int jm = i & ~(m - 1);
            float2 a = src[i];
            float2 b = src[i + 2048];
            float2 w = tw[jm];
            int d0 = i + jm;
            dst[d0] = make_float2(a.x + b.x, a.y + b.y);
            float2 d = make_float2(a.x - b.x, a.y - b.y);
            dst[d0 + m] = cmul(d, w);
        }
        float2* t = src; src = dst; dst = t;
    }
    __syncthreads();
    return src;
}
template<int MID>
__device__ float2* ifft_masked(const float2* __restrict__ tw, const float2* __restrict__ X,
                               float2* b1, float2* b2, int fs) {
    __syncthreads();
    #pragma unroll
    for (int i = threadIdx.x; i < 2048; i += 512) {
        float m0 = maskval<MID>(i, fs);
        float m1 = maskval<MID>(i + 2048, fs);
        float2 a = X[i];        a.x *= m0; a.y *= m0;
        float2 b = X[i + 2048]; b.x *= m1; b.y *= m1;
        float2 w = tw[i]; w.y = -w.y;
        b1[2*i]   = make_float2(a.x + b.x, a.y + b.y);
        float2 d = make_float2(a.x - b.x, a.y - b.y);
        b1[2*i+1] = cmul(d, w);
    }
    float2* src = b1; float2* dst = b2;
    #pragma unroll 1
    for (int s = 1; s < 12; s++) {
        int m = 1 << s;
        __syncthreads();
        #pragma unroll
        for (int i = threadIdx.x; i < 2048; i += 512) {
            int jm = i & ~(m - 1);
            float2 a = src[i];
            float2 b = src[i + 2048];
            float2 w = tw[jm]; w.y = -w.y;
            int d0 = i + jm;
            dst[d0] = make_float2(a.x + b.x, a.y + b.y);
            float2 d = make_float2(a.x - b.x, a.y - b.y);
            dst[d0 + m] = cmul(d, w);
        }
        float2* t = src; src = dst; dst = t;
    }
    __syncthreads();
    return src;
}

// ---------------- kernel 0: init ----------------
__global__ void init_kernel(const float* __restrict__ b) {
    int i = blockIdx.x * blockDim.x + threadIdx.x;
    if (i < 320 * FD) g_feats[i] = b[i & 511];
    if (i == 0) { g_cons = 0.0f; g_contr = 0.0f; }
}

// ---------------- kernel 1: build 5 views (fp32) ----------------
__global__ void __launch_bounds__(512, 1)
views_kernel(const float* __restrict__ x, const float* __restrict__ nz1,
             const float* __restrict__ nz2,
             const int* __restrict__ pfs, const int* __restrict__ pts) {
    extern __shared__ float2 smx[];
    float2* tw = smx;
    float2* bA = smx + 2048;
    float2* bB = bA + 4096;
    float2* bC = bB + 4096;
    __shared__ float red[32];

    const int row = blockIdx.x;
    const int bi = row >> 6, ci = row & 63;
    const int tid = threadIdx.x;
    const int fs = *pfs, ts = *pts;
    const size_t xbase = (size_t)row * TT;

    float* A0 = g_A + (size_t)(0*64 + bi) * KTOT + (size_t)ci * TT;
    float* A1 = g_A + (size_t)(1*64 + bi) * KTOT + (size_t)ci * TT;
    float* A2 = g_A + (size_t)(2*64 + bi) * KTOT + (size_t)ci * TT;
    float* A3 = g_A + (size_t)(3*64 + bi) * KTOT + (size_t)ci * TT;
    float* A4 = g_A + (size_t)(4*64 + bi) * KTOT + (size_t)ci * TT;

    for (int k = tid; k < 2048; k += 512) {
        float s, c;
        sincospif(-(float)k * (1.0f / 2048.0f), &s, &c);
        tw[k] = make_float2(c, s);
    }

    float ls = 0.0f, lq = 0.0f;
    for (int t = tid; t < TT; t += 512) {
        float v = x[xbase + t];
        bA[t] = make_float2(v, 0.0f);
        A0[t] = v;
        ls += v; lq += v * v;
    }
    float s1 = blockReduceSum(ls, red);
    float q1 = blockReduceSum(lq, red);
    float std1 = sqrtf(fmaxf(0.0f, (q1 - s1 * s1 * (1.0f / 4096.0f)) * (1.0f / 4095.0f)));

    for (int t = tid; t < TT; t += 512)
        A3[t] = x[xbase + t] + nz1[xbase + t] * (0.02f * std1);

    fft_fwd(tw, bA, bB);

    float2* r = ifft_masked<0>(tw, bA, bB, bC, fs);
    for (int t = tid; t < TT; t += 512)
        A1[t] = r[t].x * (1.0f / 4096.0f);

    r = ifft_masked<1>(tw, bA, bB, bC, fs);
    for (int t = tid; t < TT; t += 512) {
        float tm = (t >= ts && t < ts + 204) ? 0.1f : 1.0f;
        A2[t] = tm * r[t].x * (1.0f / 4096.0f);
    }

    r = ifft_masked<2>(tw, bA, bB, bC, fs);
    ls = 0.0f; lq = 0.0f;
    for (int t = tid; t < TT; t += 512) {
        float tm = (t >= ts && t < ts + 204) ? 0.1f : 1.0f;
        float v = tm * r[t].x * (1.0f / 4096.0f);
        ls += v; lq += v * v;
    }
    float s2 = blockReduceSum(ls, red);
    float q2 = blockReduceSum(lq, red);
    float std2 = sqrtf(fmaxf(0.0f, (q2 - s2 * s2 * (1.0f / 4096.0f)) * (1.0f / 4095.0f)));
    for (int t = tid; t < TT; t += 512) {
        float tm = (t >= ts && t < ts + 204) ? 0.1f : 1.0f;
        float v = tm * r[t].x * (1.0f / 4096.0f);
        A4[t] = v + nz2[xbase + t] * (0.02f * std2);
    }
}

// ---------------- kernel 2: mma.sync bf16-split GEMM ----------------
// feats[320,512] += A[320,K] * W[K,512], 3-term hi/lo split.
// CTA tile 64x128, 128 threads (4 warps as 2x2 of 32x64), k-chunk 32.
// smem: A planes [64][32] bf16 (row 64B, chunk swizzle (kb + (m>>1))&3),
//       W planes [32][128] bf16 (row 256B, chunk swizzle nb ^ (k&7)).
#define SA_H 0
#define SA_L 4096
#define SW_H 8192
#define SW_L 16384
#define GSM 24576

__global__ void __launch_bounds__(128, 3) gemm_kernel(const float* __restrict__ Wm) {
    __shared__ __align__(1024) char smbuf[GSM];
    const uint32_t sb = smem_to_u32(smbuf);

    const int tid = threadIdx.x;
    const int warp = tid >> 5, lane = tid & 31;
    const int m0 = blockIdx.y * 64;
    const int n0 = blockIdx.x * 128;
    const int z = blockIdx.z;
    const int start_chunk = 372 * z + (z < 8 ? z : 8);
    const int nchunks = 372 + (z < 8 ? 1 : 0);

    const int wm = warp >> 1;        // 0..1 -> m offset 32*wm
    const int wn = warp & 1;         // 0..1 -> n offset 64*wn

    float acc[2][8][4];
    #pragma unroll
    for (int a = 0; a < 2; a++)
        #pragma unroll
        for (int b = 0; b < 8; b++)
            #pragma unroll
            for (int c = 0; c < 4; c++) acc[a][b][c] = 0.0f;

    // precompute per-thread smem store offsets
    // A: 4 float4/thread: f = tid + 128*i -> m = f>>3, k4 = f&7
    uint32_t a_off[4]; size_t a_src[4];
    #pragma unroll
    for (int i = 0; i < 4; i++) {
        int f = tid + 128 * i;
        int m = f >> 3, k4 = f & 7;
        a_off[i] = (uint32_t)(m * 64 + ((((k4 >> 1) + (m >> 1)) & 3) << 4) + ((k4 & 1) << 3));
        a_src[i] = (size_t)(m0 + m) * KTOT + (size_t)k4 * 4;
    }
    // W: 8 float4/thread: f = tid + 128*i -> k = f>>5, n4 = f&31
    uint32_t w_off[8]; size_t w_src[8];
    #pragma unroll
    for (int i = 0; i < 8; i++) {
        int f = tid + 128 * i;
        int k = f >> 5, n4 = f & 31;
        w_off[i] = (uint32_t)(k * 256 + ((((n4 >> 1) ^ (k & 7)) & 15) << 4) + ((n4 & 1) << 3));
        w_src[i] = (size_t)k * 512 + (size_t)(n0 + n4 * 4);
    }

    // precompute ldmatrix addresses (per lane)
    // A frags: [mt][kt][plane]; lane -> tile=lane>>3, r=lane&7
    uint32_t a_ld[2][2];
    {
        int tile = lane >> 3, r = lane & 7;
        #pragma unroll
        for (int mt = 0; mt < 2; mt++)
            #pragma unroll
            for (int kt = 0; kt < 2; kt++) {
                int mm = wm * 32 + mt * 16 + (tile & 1) * 8 + r;
                int kb = kt * 2 + (tile >> 1);
                a_ld[mt][kt] = sb + (uint32_t)(mm * 64 + (((kb + (mm >> 1)) & 3) << 4));
            }
    }
    // B frags: [nt][kt]; lanes 0..15 -> k row
    uint32_t b_ld[8][2];
    {
        int lr = lane & 15;
        #pragma unroll
        for (int nt = 0; nt < 8; nt++) {
            int nb = wn * 8 + nt;
            #pragma unroll
            for (int kt = 0; kt < 2; kt++) {
                int k = kt * 16 + lr;
                b_ld[nt][kt] = sb + (uint32_t)(k * 256 + (((nb ^ (k & 7)) & 15) << 4));
            }
        }
    }

    const float* __restrict__ Ag = g_A;

    for (int it = 0; it < nchunks; ++it) {
        const size_t kk = (size_t)(start_chunk + it) * 32;

        // ---- load + convert + store smem ----
        #pragma unroll
        for (int i = 0; i < 4; i++) {
            float4 v = *(const float4*)(Ag + a_src[i] + kk);
            uint32_t h0, l0, h1, l1;
            split2(v.x, v.y, h0, l0);
            split2(v.z, v.w, h1, l1);
            *(uint2*)(smbuf + SA_H + a_off[i]) = make_uint2(h0, h1);
            *(uint2*)(smbuf + SA_L + a_off[i]) = make_uint2(l0, l1);
        }
        #pragma unroll
        for (int i = 0; i < 8; i++) {
            float4 v = *(const float4*)(Wm + w_src[i] + kk * 512);
            uint32_t h0, l0, h1, l1;
            split2(v.x, v.y, h0, l0);
            split2(v.z, v.w, h1, l1);
            *(uint2*)(smbuf + SW_H + w_off[i]) = make_uint2(h0, h1);
            *(uint2*)(smbuf + SW_L + w_off[i]) = make_uint2(l0, l1);
        }
        __syncthreads();

        // ---- mma ----
        #pragma unroll
        for (int kt = 0; kt < 2; kt++) {
            uint32_t ah[2][4], al[2][4];
            #pragma unroll
            for (int mt = 0; mt < 2; mt++) {
                ldsm_x4(ah[mt], a_ld[mt][kt] + SA_H);
                ldsm_x4(al[mt], a_ld[mt][kt] + SA_L);
            }
            uint32_t bh[8][2], bl[8][2];
            #pragma unroll
            for (int nt = 0; nt < 8; nt++) {
                ldsm_x2_trans(bh[nt], b_ld[nt][kt] + SW_H);
                ldsm_x2_trans(bl[nt], b_ld[nt][kt] + SW_L);
            }
            #pragma unroll
            for (int mt = 0; mt < 2; mt++)
                #pragma unroll
                for (int nt = 0; nt < 8; nt++) {
                    mma_bf16(acc[mt][nt], ah[mt], bh[nt]);
                    mma_bf16(acc[mt][nt], ah[mt], bl[nt]);
                    mma_bf16(acc[mt][nt], al[mt], bh[nt]);
                }
        }
        __syncthreads();
    }

    // ---- epilogue: atomic accumulate into g_feats ----
    {
        const int g = lane >> 2, t4 = lane & 3;
        #pragma unroll
        for (int mt = 0; mt < 2; mt++) {
            int r0 = m0 + wm * 32 + mt * 16 + g;
            int r1 = r0 + 8;
            #pragma unroll
            for (int nt = 0; nt < 8; nt++) {
                int col = n0 + wn * 64 + nt * 8 + t4 * 2;
                atomicAdd(&g_feats[r0 * 512 + col],     acc[mt][nt][0]);
                atomicAdd(&g_feats[r0 * 512 + col + 1], acc[mt][nt][1]);
                atomicAdd(&g_feats[r1 * 512 + col],     acc[mt][nt][2]);
                atomicAdd(&g_feats[r1 * 512 + col + 1], acc[mt][nt][3]);
            }
        }
    }
}

// ---------------- kernel 3: row norms + consistency ----------------
__global__ void post_kernel() {
    __shared__ float red[32];
    const int i = blockIdx.x;
    const int tid = threadIdx.x;
    const int base = i * 512;
    const int b0 = (i & 63) * 512;
    float sq = 0.0f, dsq = 0.0f;
    for (int f = tid; f < 512; f += 256) {
        float v = g_feats[base + f];
        sq += v * v;
        if (i >= 64) {
            float d = v - g_feats[b0 + f];
            dsq += d * d;
        }
    }
    float tsq = blockReduceSum(sq, red);
    float tdq = blockReduceSum(dsq, red);
    if (tid == 0) {
        g_norms[i] = sqrtf(tsq);
        if (i >= 64) atomicAdd(&g_cons, tdq);
    }
}

// ---------------- kernel 4: contrastive ----------------
__global__ void contr_kernel() {
    __shared__ float fi[512];
    __shared__ float simb[320];
    __shared__ float red[32];
    const int i = blockIdx.x;
    const int tid = threadIdx.x;
    for (int f = tid; f < 512; f += 256) fi[f] = g_feats[i * 512 + f];
    __syncthreads();
    const float inv_i = 1.0f / g_norms[i];
    const int w = tid >> 5, lane = tid & 31;
    for (int j = w; j < 320; j += 8) {
        float s = 0.0f;
        const float* fj = g_feats + j * 512;
        #pragma unroll 4
        for (int e = lane; e < 512; e += 32) s += fi[e] * fj[e];
        #pragma unroll
        for (int o = 16; o; o >>= 1) s += __shfl_down_sync(0xffffffffu, s, o);
        if (lane == 0) simb[j] = s * inv_i / g_norms[j] * 10.0f;
    }
    __syncthreads();
    float mx = -3.4e38f;
    for (int j = tid; j < 320; j += 256) mx = fmaxf(mx, simb[j]);
    mx = blockReduceMax(mx, red);
    float se = 0.0f;
    for (int j = tid; j < 320; j += 256) se += expf(simb[j] - mx);
    se = blockReduceSum(se, red);
    if (tid == 0) {
        float lse = mx + logf(se);
        float c = 0.0f;
        if (i > 0)   c += lse - simb[i - 1];
        if (i < 319) c += lse - simb[i + 1];
        atomicAdd(&g_contr, c);
    }
}

// ---------------- kernel 5: finalize ----------------
__global__ void fin_kernel(float* __restrict__ out) {
    out[0] = g_cons * (1.0f / 131072.0f) + 0.5f * (g_contr * (1.0f / 638.0f));
}

// ---------------- launch ----------------
extern "C" void kernel_launch(void* const* d_in, const int* in_sizes, int n_in,
                              void* d_out, int out_size) {
    const float* x  = (const float*)d_in[0];
    const float* W  = (const float*)d_in[1];
    const float* b  = (const float*)d_in[2];
    const float* n1 = (const float*)d_in[3];
    const float* n2 = (const float*)d_in[4];
    const int* fs   = (const int*)d_in[5];
    const int* ts   = (const int*)d_in[6];
    (void)in_sizes; (void)n_in; (void)out_size;

    cudaFuncSetAttribute(views_kernel, cudaFuncAttributeMaxDynamicSharedMemorySize, 114688);

    init_kernel<<<640, 256>>>(b);
    views_kernel<<<4096, 512, 114688>>>(x, n1, n2, fs, ts);
    gemm_kernel<<<dim3(4, 5, 22), 128>>>(W);
    post_kernel<<<320, 256>>>();
    contr_kernel<<<320, 256>>>();
    fin_kernel<<<1, 1>>>((float*)d_out);
}